// round 14
// baseline (speedup 1.0000x reference)
#include <cuda_runtime.h>
#include <cstdint>

// Problem constants
constexpr int NN   = 100000;   // nodes
constexpr int EE   = 1600000;  // edges
constexpr int IND  = 256;
constexpr int HIDD = 128;
constexpr int OUTD = 32;

typedef unsigned long long ull;

// Scratch (static device arrays; no allocation allowed)
__device__ ull   g_pdeg[NN];       // packed: cnt<<40 | fixed-point(sum w, 2^20)
__device__ int   g_cnt[NN];        // in-edge count per dst (no self-loop)
__device__ int   g_off[NN];        // CSR row offsets (exclusive prefix of cnt)
__device__ int   g_cur[NN];        // fill cursors
__device__ float g_inv[NN];        // deg^{-1/2}
__device__ int2  g_edge[EE];       // CSR: {src, __float_as_int(norm)} per slot
__device__ float g_h1[(size_t)NN * HIDD];   // x @ W1
__device__ float g_h2[(size_t)NN * OUTD];   // relu(x_emb) @ W2

// ---------------------------------------------------------------------------
// per-block edge dtype probe: true int64 edge_index values all lie in [0,NN);
// int32 read as int64 fuses two indices -> huge values. 16 probes, L2-hit.
// ---------------------------------------------------------------------------
__device__ __forceinline__ int block_probe_is32(const long long* __restrict__ ei,
                                                int* s_flag) {
    if (threadIdx.x == 0) {
        int ok = 1;
        for (int t = 0; t < 16; t++) {
            long long v = ei[t];
            if (v < 0 || v >= NN) { ok = 0; break; }
        }
        *s_flag = ok ? 0 : 1;
    }
    __syncthreads();
    return *s_flag;
}

__device__ __forceinline__ int load_idx(const long long* ei, size_t pos, int is32) {
    return is32 ? ((const int*)ei)[pos] : (int)ei[pos];
}

// ---------------------------------------------------------------------------
// degree+count in ONE packed atomic per edge. g_pdeg starts zero (static init
// on first call; k_scan resets it each call for the next graph replay).
// ---------------------------------------------------------------------------
__global__ void k_deg(const long long* __restrict__ ei, const float* __restrict__ ew) {
    __shared__ int s_is32;
    int is32 = block_probe_is32(ei, &s_is32);
    int e = blockIdx.x * blockDim.x + threadIdx.x;
    if (e < EE) {
        int d = load_idx(ei, (size_t)EE + e, is32);
        if ((unsigned)d < (unsigned)NN) {
            unsigned wq = __float2uint_rn(ew[e] * 1048576.0f);   // 2^20 fixed point
            atomicAdd(&g_pdeg[d], ((ull)1 << 40) | (ull)wq);
        }
    }
}

// single block: unpack pdeg -> cnt/inv, reset pdeg, exclusive scan -> off/cur
__global__ void k_scan() {
    __shared__ int sums[1024];
    const int T  = 1024;
    const int CH = (NN + T - 1) / T;      // 98
    int t  = threadIdx.x;
    int lo = t * CH;
    int hi = lo + CH < NN ? lo + CH : NN;
    int s = 0;
    for (int i = lo; i < hi; i++) {
        ull p = g_pdeg[i];
        g_pdeg[i] = 0;                                // reset for next replay
        int c = (int)(p >> 40);
        float d = 1.0f + (float)(p & 0xFFFFFFFFFFull) * (1.0f / 1048576.0f);
        g_inv[i] = rsqrtf(d);                         // d >= 1 always
        g_cnt[i] = c;
        s += c;
    }
    sums[t] = s;
    __syncthreads();
    if (t == 0) {
        int run = 0;
        for (int i = 0; i < T; i++) { int v = sums[i]; sums[i] = run; run += v; }
    }
    __syncthreads();
    int run = sums[t];
    for (int i = lo; i < hi; i++) {
        g_off[i] = run;
        g_cur[i] = run;
        run += g_cnt[i];
    }
}

// scatter edges into CSR slots; one packed 8B store per edge
__global__ void k_fill(const long long* __restrict__ ei, const float* __restrict__ ew) {
    __shared__ int s_is32;
    int is32 = block_probe_is32(ei, &s_is32);
    int e = blockIdx.x * blockDim.x + threadIdx.x;
    if (e < EE) {
        int s = load_idx(ei, (size_t)e, is32);
        int d = load_idx(ei, (size_t)EE + e, is32);
        if ((unsigned)s < (unsigned)NN && (unsigned)d < (unsigned)NN) {
            int pos = atomicAdd(&g_cur[d], 1);
            float nw = g_inv[s] * ew[e] * g_inv[d];
            g_edge[pos] = make_int2(s, __float_as_int(nw));
        }
    }
}

// ---------------------------------------------------------------------------
// Tiled fp32 GEMM with register-prefetch pipelining:
// H[M, BN] = op(X)[M, KK] @ W[KK, BN]
// 256 threads, BM=128 rows. Thread grid TX x TY (TX = BN/TN). Micro TM x TN.
// Next tile's GMEM loads are issued into registers BEFORE the compute loop,
// overlapping DRAM/L2 latency with FMA work; regs -> smem after compute.
// Invariants: BN % TN == 0; 256 % (BN/TN) == 0; (256/(BN/TN)) * TM == 128;
// TM % 4 == 0; TN % 4 == 0. Both instantiations below satisfy these.
// DSTBUF: 1 -> g_h1, 2 -> g_h2
// ---------------------------------------------------------------------------
template <int KK, int BN, int TM, int TN, bool RELU, int DSTBUF>
__global__ __launch_bounds__(256, 2)
void k_gemm(const float* __restrict__ X, const float* __restrict__ W) {
    float* __restrict__ H = (DSTBUF == 1) ? g_h1 : g_h2;

    constexpr int KT = 16;
    constexpr int BM = 128;
    constexpr int TX = BN / TN;           // 16 (gemm1) / 8 (gemm2)
    constexpr int TY = 256 / TX;          // 16 / 32
    constexpr int XPT = BM * KT / 4 / 256;            // X float4 per thread = 2
    constexpr int WF4 = KT * BN / 4;                  // 512 (gemm1) / 128 (gemm2)
    constexpr int WPT = (WF4 + 255) / 256;            // 2 / 1

    __shared__ __align__(16) float As[KT][BM + 4];    // [k][row], padded
    __shared__ __align__(16) float Bs[KT][BN];

    int tid  = threadIdx.x;
    int tx   = tid % TX;
    int ty   = tid / TX;
    int row0 = blockIdx.x * BM;

    float acc[TM][TN];
#pragma unroll
    for (int i = 0; i < TM; i++)
#pragma unroll
        for (int j = 0; j < TN; j++) acc[i][j] = 0.0f;

    float4 xs[XPT];
    float4 ws[WPT];

    // ---- prologue: g2r for tile 0 ----
#pragma unroll
    for (int l = 0; l < XPT; l++) {
        int idx = tid + l * 256;
        int r   = idx >> 2;
        int gr  = row0 + r;
        xs[l] = make_float4(0.f, 0.f, 0.f, 0.f);
        if (gr < NN) xs[l] = *(const float4*)(X + (size_t)gr * KK + ((idx & 3) << 2));
    }
#pragma unroll
    for (int l = 0; l < WPT; l++) {
        int idx = tid + l * 256;
        if (idx < WF4) {
            int kk = idx / (BN / 4);
            int cc = (idx % (BN / 4)) * 4;
            ws[l] = *(const float4*)(W + (size_t)kk * BN + cc);
        }
    }

    for (int k0 = 0; k0 < KK; k0 += KT) {
        // ---- r2s: staged regs -> smem (RELU applied here for X) ----
#pragma unroll
        for (int l = 0; l < XPT; l++) {
            int idx = tid + l * 256;
            int r   = idx >> 2;
            int kc  = (idx & 3) << 2;
            float4 v = xs[l];
            if (RELU) {
                v.x = fmaxf(v.x, 0.f); v.y = fmaxf(v.y, 0.f);
                v.z = fmaxf(v.z, 0.f); v.w = fmaxf(v.w, 0.f);
            }
            As[kc + 0][r] = v.x; As[kc + 1][r] = v.y;
            As[kc + 2][r] = v.z; As[kc + 3][r] = v.w;
        }
#pragma unroll
        for (int l = 0; l < WPT; l++) {
            int idx = tid + l * 256;
            if (idx < WF4) {
                int kk = idx / (BN / 4);
                int cc = (idx % (BN / 4)) * 4;
                *(float4*)(&Bs[kk][cc]) = ws[l];
            }
        }
        __syncthreads();

        // ---- g2r for next tile (loads in flight during compute) ----
        int kn = k0 + KT;
        if (kn < KK) {
#pragma unroll
            for (int l = 0; l < XPT; l++) {
                int idx = tid + l * 256;
                int r   = idx >> 2;
                int gr  = row0 + r;
                xs[l] = make_float4(0.f, 0.f, 0.f, 0.f);
                if (gr < NN)
                    xs[l] = *(const float4*)(X + (size_t)gr * KK + kn + ((idx & 3) << 2));
            }
#pragma unroll
            for (int l = 0; l < WPT; l++) {
                int idx = tid + l * 256;
                if (idx < WF4) {
                    int kk = idx / (BN / 4);
                    int cc = (idx % (BN / 4)) * 4;
                    ws[l] = *(const float4*)(W + (size_t)(kn + kk) * BN + cc);
                }
            }
        }

        // ---- compute ----
#pragma unroll
        for (int k = 0; k < KT; k++) {
            float a[TM], b[TN];
#pragma unroll
            for (int i = 0; i < TM / 4; i++)
                *(float4*)(a + 4 * i) = *(const float4*)(&As[k][ty * TM + 4 * i]);
#pragma unroll
            for (int j = 0; j < TN / 4; j++)
                *(float4*)(b + 4 * j) = *(const float4*)(&Bs[k][tx * TN + 4 * j]);
#pragma unroll
            for (int i = 0; i < TM; i++)
#pragma unroll
                for (int j = 0; j < TN; j++) acc[i][j] += a[i] * b[j];
        }
        __syncthreads();
    }

#pragma unroll
    for (int i = 0; i < TM; i++) {
        int gr = row0 + ty * TM + i;
        if (gr < NN) {
#pragma unroll
            for (int j = 0; j < TN / 4; j++) {
                float4 v = make_float4(acc[i][4 * j], acc[i][4 * j + 1],
                                       acc[i][4 * j + 2], acc[i][4 * j + 3]);
                *(float4*)(H + (size_t)gr * BN + tx * TN + 4 * j) = v;
            }
        }
    }
}

// ---------------------------------------------------------------------------
// CSR aggregation, layer 1 (R10 unroll-4 body — low register pressure):
// one warp per node, lane owns a float4 chunk.
// out = sum_{e in in(n)} norm_e * h1[src_e] + inv(n)^2 * h1[n] + b1
// ---------------------------------------------------------------------------
__global__ void k_agg1(float* __restrict__ xemb, const float* __restrict__ b1) {
    int warp = (blockIdx.x * blockDim.x + threadIdx.x) >> 5;
    int lane = threadIdx.x & 31;
    if (warp >= NN) return;

    int beg = g_off[warp];
    int cnt = g_cnt[warp];
    float iv = g_inv[warp];
    float inv2 = iv * iv;

    size_t off = (size_t)warp * HIDD + lane * 4;
    float4 h = *(const float4*)(g_h1 + off);
    float4 b = *(const float4*)(b1 + lane * 4);
    float4 acc;
    acc.x = inv2 * h.x + b.x;
    acc.y = inv2 * h.y + b.y;
    acc.z = inv2 * h.z + b.z;
    acc.w = inv2 * h.w + b.w;

    int i = 0;
    for (; i + 4 <= cnt; i += 4) {
        int2 p0 = g_edge[beg + i + 0], p1 = g_edge[beg + i + 1];
        int2 p2 = g_edge[beg + i + 2], p3 = g_edge[beg + i + 3];
        float n0 = __int_as_float(p0.y), n1 = __int_as_float(p1.y);
        float n2 = __int_as_float(p2.y), n3 = __int_as_float(p3.y);
        float4 v0 = *(const float4*)(g_h1 + (size_t)p0.x * HIDD + lane * 4);
        float4 v1 = *(const float4*)(g_h1 + (size_t)p1.x * HIDD + lane * 4);
        float4 v2 = *(const float4*)(g_h1 + (size_t)p2.x * HIDD + lane * 4);
        float4 v3 = *(const float4*)(g_h1 + (size_t)p3.x * HIDD + lane * 4);
        acc.x += n0 * v0.x + n1 * v1.x + n2 * v2.x + n3 * v3.x;
        acc.y += n0 * v0.y + n1 * v1.y + n2 * v2.y + n3 * v3.y;
        acc.z += n0 * v0.z + n1 * v1.z + n2 * v2.z + n3 * v3.z;
        acc.w += n0 * v0.w + n1 * v1.w + n2 * v2.w + n3 * v3.w;
    }
    for (; i < cnt; i++) {
        int2 p = g_edge[beg + i];
        float nw = __int_as_float(p.y);
        float4 v = *(const float4*)(g_h1 + (size_t)p.x * HIDD + lane * 4);
        acc.x += nw * v.x; acc.y += nw * v.y;
        acc.z += nw * v.z; acc.w += nw * v.w;
    }
    *(float4*)(xemb + off) = acc;
}

// layer 2: 32 features -> one float per lane (R10 unroll-4 body)
__global__ void k_agg2(float* __restrict__ outp, const float* __restrict__ b2) {
    int warp = (blockIdx.x * blockDim.x + threadIdx.x) >> 5;
    int lane = threadIdx.x & 31;
    if (warp >= NN) return;

    int beg = g_off[warp];
    int cnt = g_cnt[warp];
    float iv = g_inv[warp];
    float inv2 = iv * iv;

    size_t off = (size_t)warp * OUTD + lane;
    float acc = inv2 * g_h2[off] + b2[lane];

    int i = 0;
    for (; i + 4 <= cnt; i += 4) {
        int2 p0 = g_edge[beg + i + 0], p1 = g_edge[beg + i + 1];
        int2 p2 = g_edge[beg + i + 2], p3 = g_edge[beg + i + 3];
        acc += __int_as_float(p0.y) * g_h2[(size_t)p0.x * OUTD + lane]
             + __int_as_float(p1.y) * g_h2[(size_t)p1.x * OUTD + lane]
             + __int_as_float(p2.y) * g_h2[(size_t)p2.x * OUTD + lane]
             + __int_as_float(p3.y) * g_h2[(size_t)p3.x * OUTD + lane];
    }
    for (; i < cnt; i++) {
        int2 p = g_edge[beg + i];
        acc += __int_as_float(p.y) * g_h2[(size_t)p.x * OUTD + lane];
    }
    outp[off] = acc;
}

// ---------------------------------------------------------------------------
extern "C" void kernel_launch(void* const* d_in, const int* in_sizes, int n_in,
                              void* d_out, int out_size) {
    const float*     x  = (const float*)d_in[0];
    const long long* ei = (const long long*)d_in[1];   // int32 or int64 — probed
    const float*     ew = (const float*)d_in[2];
    const float*     W1 = (const float*)d_in[3];
    const float*     b1 = (const float*)d_in[4];
    const float*     W2 = (const float*)d_in[5];
    const float*     b2 = (const float*)d_in[6];

    float* outp = (float*)d_out;                       // [NN, OUTD]
    float* xemb = outp + (size_t)NN * OUTD;            // [NN, HIDD]

    const int TB = 256;
    // CSR build: deg (packed atomic, self-reset by scan), scan(+inv), fill
    k_deg<<<(EE + TB - 1) / TB, TB>>>(ei, ew);
    k_scan<<<1, 1024>>>();
    k_fill<<<(EE + TB - 1) / TB, TB>>>(ei, ew);

    // layer 1: h1 = x @ W1 ; CSR-gather aggregate (+self-loop +bias) -> xemb
    k_gemm<IND, HIDD, 8, 8, false, 1><<<(NN + 127) / 128, TB>>>(x, W1);
    k_agg1<<<(NN * 32 + TB - 1) / TB, TB>>>(xemb, b1);

    // layer 2: h2 = relu(xemb) @ W2 ; aggregate -> out
    k_gemm<HIDD, OUTD, 4, 4, true, 2><<<(NN + 127) / 128, TB>>>(xemb, W2);
    k_agg2<<<(NN * 32 + TB - 1) / TB, TB>>>(outp, b2);
}

// round 15
// speedup vs baseline: 1.1295x; 1.1295x over previous
#include <cuda_runtime.h>
#include <cstdint>

// Problem constants
constexpr int NN   = 100000;   // nodes
constexpr int EE   = 1600000;  // edges
constexpr int IND  = 256;
constexpr int HIDD = 128;
constexpr int OUTD = 32;

typedef unsigned long long ull;

// Scratch (static device arrays; no allocation allowed)
__device__ ull   g_pdeg[NN];       // packed: cnt<<40 | fixed-point(sum w, 2^20)
__device__ int   g_cnt[NN];        // in-edge count per dst (no self-loop)
__device__ int   g_off[NN];        // CSR row offsets (exclusive prefix of cnt)
__device__ int   g_cur[NN];        // fill cursors
__device__ float g_inv[NN];        // deg^{-1/2}
__device__ int2  g_edge[EE];       // CSR: {src, __float_as_int(norm)} per slot
__device__ float g_h1[(size_t)NN * HIDD];   // x @ W1
__device__ float g_h2[(size_t)NN * OUTD];   // relu(x_emb) @ W2

// ---------------------------------------------------------------------------
// per-block edge dtype probe: true int64 edge_index values all lie in [0,NN);
// int32 read as int64 fuses two indices -> huge values. 16 probes, L2-hit.
// ---------------------------------------------------------------------------
__device__ __forceinline__ int block_probe_is32(const long long* __restrict__ ei,
                                                int* s_flag) {
    if (threadIdx.x == 0) {
        int ok = 1;
        for (int t = 0; t < 16; t++) {
            long long v = ei[t];
            if (v < 0 || v >= NN) { ok = 0; break; }
        }
        *s_flag = ok ? 0 : 1;
    }
    __syncthreads();
    return *s_flag;
}

__device__ __forceinline__ int load_idx(const long long* ei, size_t pos, int is32) {
    return is32 ? ((const int*)ei)[pos] : (int)ei[pos];
}

// ---------------------------------------------------------------------------
// degree+count in ONE packed atomic per edge. g_pdeg starts zero (static init
// on first call; k_scan resets it each call for the next graph replay).
// ---------------------------------------------------------------------------
__global__ void k_deg(const long long* __restrict__ ei, const float* __restrict__ ew) {
    __shared__ int s_is32;
    int is32 = block_probe_is32(ei, &s_is32);
    int e = blockIdx.x * blockDim.x + threadIdx.x;
    if (e < EE) {
        int d = load_idx(ei, (size_t)EE + e, is32);
        if ((unsigned)d < (unsigned)NN) {
            unsigned wq = __float2uint_rn(ew[e] * 1048576.0f);   // 2^20 fixed point
            atomicAdd(&g_pdeg[d], ((ull)1 << 40) | (ull)wq);
        }
    }
}

// single block: unpack pdeg -> cnt/inv, reset pdeg, exclusive scan -> off/cur
__global__ void k_scan() {
    __shared__ int sums[1024];
    const int T  = 1024;
    const int CH = (NN + T - 1) / T;      // 98
    int t  = threadIdx.x;
    int lo = t * CH;
    int hi = lo + CH < NN ? lo + CH : NN;
    int s = 0;
    for (int i = lo; i < hi; i++) {
        ull p = g_pdeg[i];
        g_pdeg[i] = 0;                                // reset for next replay
        int c = (int)(p >> 40);
        float d = 1.0f + (float)(p & 0xFFFFFFFFFFull) * (1.0f / 1048576.0f);
        g_inv[i] = rsqrtf(d);                         // d >= 1 always
        g_cnt[i] = c;
        s += c;
    }
    sums[t] = s;
    __syncthreads();
    if (t == 0) {
        int run = 0;
        for (int i = 0; i < T; i++) { int v = sums[i]; sums[i] = run; run += v; }
    }
    __syncthreads();
    int run = sums[t];
    for (int i = lo; i < hi; i++) {
        g_off[i] = run;
        g_cur[i] = run;
        run += g_cnt[i];
    }
}

// scatter edges into CSR slots; one packed 8B store per edge
__global__ void k_fill(const long long* __restrict__ ei, const float* __restrict__ ew) {
    __shared__ int s_is32;
    int is32 = block_probe_is32(ei, &s_is32);
    int e = blockIdx.x * blockDim.x + threadIdx.x;
    if (e < EE) {
        int s = load_idx(ei, (size_t)e, is32);
        int d = load_idx(ei, (size_t)EE + e, is32);
        if ((unsigned)s < (unsigned)NN && (unsigned)d < (unsigned)NN) {
            int pos = atomicAdd(&g_cur[d], 1);
            float nw = g_inv[s] * ew[e] * g_inv[d];
            g_edge[pos] = make_int2(s, __float_as_int(nw));
        }
    }
}

// ---------------------------------------------------------------------------
// tf32 round-to-nearest conversion (result stays in a 32-bit float container)
// ---------------------------------------------------------------------------
__device__ __forceinline__ float to_tf32(float f) {
    unsigned o;
    asm("cvt.rna.tf32.f32 %0, %1;" : "=r"(o) : "f"(f));
    return __uint_as_float(o);
}

// ---------------------------------------------------------------------------
// GEMM1 via tensor cores: h1[M,128] = x[M,256] @ W1[256,128]
// mma.sync.aligned.m16n8k8 tf32. Block 128x128, 8 warps (4x2), warp 32x64.
// smem padded stride 136 (136 mod 32 == 8) -> fragment loads conflict-free.
// ---------------------------------------------------------------------------
__global__ __launch_bounds__(256)
void k_gemm1_tf32(const float* __restrict__ X, const float* __restrict__ W) {
    constexpr int KK = IND;               // 256
    constexpr int BM = 128, BN = 128, KT = 32;
    constexpr int LDA = BM + 8;           // 136
    constexpr int LDB = BN + 8;           // 136

    __shared__ __align__(16) float As[KT][LDA];   // [k][m] (transposed)
    __shared__ __align__(16) float Bs[KT][LDB];   // [k][n]

    int tid  = threadIdx.x;
    int lane = tid & 31, wid = tid >> 5;
    int wm   = wid & 3,  wn  = wid >> 2;   // warp grid 4 (M) x 2 (N)
    int g    = lane >> 2, c  = lane & 3;
    int row0 = blockIdx.x * BM;

    float d[2][8][4];
#pragma unroll
    for (int mt = 0; mt < 2; mt++)
#pragma unroll
        for (int nt = 0; nt < 8; nt++)
#pragma unroll
            for (int r = 0; r < 4; r++) d[mt][nt][r] = 0.0f;

    for (int k0 = 0; k0 < KK; k0 += KT) {
        // A g2s: BM*KT/4 = 1024 float4, 4 per thread; cvt to tf32 on the way
#pragma unroll
        for (int l = 0; l < 4; l++) {
            int idx = tid + l * 256;
            int r   = idx >> 3;                  // 8 float4 per row of KT
            int kc  = (idx & 7) << 2;
            int gr  = row0 + r;
            float4 v = make_float4(0.f, 0.f, 0.f, 0.f);
            if (gr < NN) v = *(const float4*)(X + (size_t)gr * KK + k0 + kc);
            As[kc + 0][r] = to_tf32(v.x);
            As[kc + 1][r] = to_tf32(v.y);
            As[kc + 2][r] = to_tf32(v.z);
            As[kc + 3][r] = to_tf32(v.w);
        }
        // B g2s: KT*BN/4 = 1024 float4, 4 per thread
#pragma unroll
        for (int l = 0; l < 4; l++) {
            int idx = tid + l * 256;
            int kk  = idx >> 5;                  // BN/4 = 32 float4 per row
            int cc  = (idx & 31) << 2;
            float4 v = *(const float4*)(W + (size_t)(k0 + kk) * BN + cc);
            float4 t = make_float4(to_tf32(v.x), to_tf32(v.y),
                                   to_tf32(v.z), to_tf32(v.w));
            *(float4*)(&Bs[kk][cc]) = t;
        }
        __syncthreads();

#pragma unroll
        for (int ks = 0; ks < KT; ks += 8) {
            unsigned a[2][4];
#pragma unroll
            for (int mt = 0; mt < 2; mt++) {
                int m0 = wm * 32 + mt * 16;
                a[mt][0] = __float_as_uint(As[ks + c    ][m0 + g    ]);
                a[mt][1] = __float_as_uint(As[ks + c    ][m0 + g + 8]);
                a[mt][2] = __float_as_uint(As[ks + c + 4][m0 + g    ]);
                a[mt][3] = __float_as_uint(As[ks + c + 4][m0 + g + 8]);
            }
            unsigned b[8][2];
#pragma unroll
            for (int nt = 0; nt < 8; nt++) {
                int n0 = wn * 64 + nt * 8;
                b[nt][0] = __float_as_uint(Bs[ks + c    ][n0 + g]);
                b[nt][1] = __float_as_uint(Bs[ks + c + 4][n0 + g]);
            }
#pragma unroll
            for (int mt = 0; mt < 2; mt++)
#pragma unroll
                for (int nt = 0; nt < 8; nt++) {
                    asm volatile(
                        "mma.sync.aligned.m16n8k8.row.col.f32.tf32.tf32.f32 "
                        "{%0,%1,%2,%3}, {%4,%5,%6,%7}, {%8,%9}, {%0,%1,%2,%3};"
                        : "+f"(d[mt][nt][0]), "+f"(d[mt][nt][1]),
                          "+f"(d[mt][nt][2]), "+f"(d[mt][nt][3])
                        : "r"(a[mt][0]), "r"(a[mt][1]), "r"(a[mt][2]), "r"(a[mt][3]),
                          "r"(b[nt][0]), "r"(b[nt][1]));
                }
        }
        __syncthreads();
    }

    // epilogue: c0,c1 -> (row g, cols 2c,2c+1); c2,c3 -> (row g+8)
#pragma unroll
    for (int mt = 0; mt < 2; mt++) {
        int r0 = row0 + wm * 32 + mt * 16 + g;
        int r1 = r0 + 8;
#pragma unroll
        for (int nt = 0; nt < 8; nt++) {
            int col = wn * 64 + nt * 8 + 2 * c;
            if (r0 < NN) {
                float2 v0 = make_float2(d[mt][nt][0], d[mt][nt][1]);
                *(float2*)(g_h1 + (size_t)r0 * HIDD + col) = v0;
            }
            if (r1 < NN) {
                float2 v1 = make_float2(d[mt][nt][2], d[mt][nt][3]);
                *(float2*)(g_h1 + (size_t)r1 * HIDD + col) = v1;
            }
        }
    }
}

// ---------------------------------------------------------------------------
// Scalar fp32 GEMM (plain R12 form) — used for layer 2 only.
// H[M, BN] = op(X)[M, KK] @ W[KK, BN]
// ---------------------------------------------------------------------------
template <int KK, int BN, int TM, int TN, bool RELU>
__global__ __launch_bounds__(256)
void k_gemm(const float* __restrict__ X, const float* __restrict__ W) {
    float* __restrict__ H = g_h2;

    constexpr int KT = 16;
    constexpr int BM = 128;
    constexpr int TX = BN / TN;
    constexpr int TY = 256 / TX;

    __shared__ __align__(16) float As[KT][BM + 4];
    __shared__ __align__(16) float Bs[KT][BN];

    int tid  = threadIdx.x;
    int tx   = tid % TX;
    int ty   = tid / TX;
    int row0 = blockIdx.x * BM;

    float acc[TM][TN];
#pragma unroll
    for (int i = 0; i < TM; i++)
#pragma unroll
        for (int j = 0; j < TN; j++) acc[i][j] = 0.0f;

    for (int k0 = 0; k0 < KK; k0 += KT) {
        constexpr int XF4 = BM * KT / 4;
#pragma unroll
        for (int l = 0; l < XF4 / 256; l++) {
            int idx = tid + l * 256;
            int r   = idx >> 2;
            int kc  = (idx & 3) << 2;
            int gr  = row0 + r;
            float4 v = make_float4(0.f, 0.f, 0.f, 0.f);
            if (gr < NN) v = *(const float4*)(X + (size_t)gr * KK + k0 + kc);
            if (RELU) {
                v.x = fmaxf(v.x, 0.f); v.y = fmaxf(v.y, 0.f);
                v.z = fmaxf(v.z, 0.f); v.w = fmaxf(v.w, 0.f);
            }
            As[kc + 0][r] = v.x; As[kc + 1][r] = v.y;
            As[kc + 2][r] = v.z; As[kc + 3][r] = v.w;
        }
        constexpr int WF4 = KT * BN / 4;
#pragma unroll
        for (int l = 0; l < (WF4 + 255) / 256; l++) {
            int idx = tid + l * 256;
            if (idx < WF4) {
                int kk = idx / (BN / 4);
                int cc = (idx % (BN / 4)) * 4;
                *(float4*)(&Bs[kk][cc]) = *(const float4*)(W + (size_t)(k0 + kk) * BN + cc);
            }
        }
        __syncthreads();

#pragma unroll
        for (int k = 0; k < KT; k++) {
            float a[TM], b[TN];
#pragma unroll
            for (int i = 0; i < TM / 4; i++)
                *(float4*)(a + 4 * i) = *(const float4*)(&As[k][ty * TM + 4 * i]);
#pragma unroll
            for (int j = 0; j < TN / 4; j++)
                *(float4*)(b + 4 * j) = *(const float4*)(&Bs[k][tx * TN + 4 * j]);
#pragma unroll
            for (int i = 0; i < TM; i++)
#pragma unroll
                for (int j = 0; j < TN; j++) acc[i][j] += a[i] * b[j];
        }
        __syncthreads();
    }

#pragma unroll
    for (int i = 0; i < TM; i++) {
        int gr = row0 + ty * TM + i;
        if (gr < NN) {
#pragma unroll
            for (int j = 0; j < TN / 4; j++) {
                float4 v = make_float4(acc[i][4 * j], acc[i][4 * j + 1],
                                       acc[i][4 * j + 2], acc[i][4 * j + 3]);
                *(float4*)(H + (size_t)gr * BN + tx * TN + 4 * j) = v;
            }
        }
    }
}

// ---------------------------------------------------------------------------
// CSR aggregation, layer 1 (unroll-4 body): one warp per node.
// out = sum_{e in in(n)} norm_e * h1[src_e] + inv(n)^2 * h1[n] + b1
// ---------------------------------------------------------------------------
__global__ void k_agg1(float* __restrict__ xemb, const float* __restrict__ b1) {
    int warp = (blockIdx.x * blockDim.x + threadIdx.x) >> 5;
    int lane = threadIdx.x & 31;
    if (warp >= NN) return;

    int beg = g_off[warp];
    int cnt = g_cnt[warp];
    float iv = g_inv[warp];
    float inv2 = iv * iv;

    size_t off = (size_t)warp * HIDD + lane * 4;
    float4 h = *(const float4*)(g_h1 + off);
    float4 b = *(const float4*)(b1 + lane * 4);
    float4 acc;
    acc.x = inv2 * h.x + b.x;
    acc.y = inv2 * h.y + b.y;
    acc.z = inv2 * h.z + b.z;
    acc.w = inv2 * h.w + b.w;

    int i = 0;
    for (; i + 4 <= cnt; i += 4) {
        int2 p0 = g_edge[beg + i + 0], p1 = g_edge[beg + i + 1];
        int2 p2 = g_edge[beg + i + 2], p3 = g_edge[beg + i + 3];
        float n0 = __int_as_float(p0.y), n1 = __int_as_float(p1.y);
        float n2 = __int_as_float(p2.y), n3 = __int_as_float(p3.y);
        float4 v0 = *(const float4*)(g_h1 + (size_t)p0.x * HIDD + lane * 4);
        float4 v1 = *(const float4*)(g_h1 + (size_t)p1.x * HIDD + lane * 4);
        float4 v2 = *(const float4*)(g_h1 + (size_t)p2.x * HIDD + lane * 4);
        float4 v3 = *(const float4*)(g_h1 + (size_t)p3.x * HIDD + lane * 4);
        acc.x += n0 * v0.x + n1 * v1.x + n2 * v2.x + n3 * v3.x;
        acc.y += n0 * v0.y + n1 * v1.y + n2 * v2.y + n3 * v3.y;
        acc.z += n0 * v0.z + n1 * v1.z + n2 * v2.z + n3 * v3.z;
        acc.w += n0 * v0.w + n1 * v1.w + n2 * v2.w + n3 * v3.w;
    }
    for (; i < cnt; i++) {
        int2 p = g_edge[beg + i];
        float nw = __int_as_float(p.y);
        float4 v = *(const float4*)(g_h1 + (size_t)p.x * HIDD + lane * 4);
        acc.x += nw * v.x; acc.y += nw * v.y;
        acc.z += nw * v.z; acc.w += nw * v.w;
    }
    *(float4*)(xemb + off) = acc;
}

// layer 2: 32 features -> one float per lane (unroll-4 body)
__global__ void k_agg2(float* __restrict__ outp, const float* __restrict__ b2) {
    int warp = (blockIdx.x * blockDim.x + threadIdx.x) >> 5;
    int lane = threadIdx.x & 31;
    if (warp >= NN) return;

    int beg = g_off[warp];
    int cnt = g_cnt[warp];
    float iv = g_inv[warp];
    float inv2 = iv * iv;

    size_t off = (size_t)warp * OUTD + lane;
    float acc = inv2 * g_h2[off] + b2[lane];

    int i = 0;
    for (; i + 4 <= cnt; i += 4) {
        int2 p0 = g_edge[beg + i + 0], p1 = g_edge[beg + i + 1];
        int2 p2 = g_edge[beg + i + 2], p3 = g_edge[beg + i + 3];
        acc += __int_as_float(p0.y) * g_h2[(size_t)p0.x * OUTD + lane]
             + __int_as_float(p1.y) * g_h2[(size_t)p1.x * OUTD + lane]
             + __int_as_float(p2.y) * g_h2[(size_t)p2.x * OUTD + lane]
             + __int_as_float(p3.y) * g_h2[(size_t)p3.x * OUTD + lane];
    }
    for (; i < cnt; i++) {
        int2 p = g_edge[beg + i];
        acc += __int_as_float(p.y) * g_h2[(size_t)p.x * OUTD + lane];
    }
    outp[off] = acc;
}

// ---------------------------------------------------------------------------
extern "C" void kernel_launch(void* const* d_in, const int* in_sizes, int n_in,
                              void* d_out, int out_size) {
    const float*     x  = (const float*)d_in[0];
    const long long* ei = (const long long*)d_in[1];   // int32 or int64 — probed
    const float*     ew = (const float*)d_in[2];
    const float*     W1 = (const float*)d_in[3];
    const float*     b1 = (const float*)d_in[4];
    const float*     W2 = (const float*)d_in[5];
    const float*     b2 = (const float*)d_in[6];

    float* outp = (float*)d_out;                       // [NN, OUTD]
    float* xemb = outp + (size_t)NN * OUTD;            // [NN, HIDD]

    const int TB = 256;
    // CSR build: deg (packed atomic, self-reset by scan), scan(+inv), fill
    k_deg<<<(EE + TB - 1) / TB, TB>>>(ei, ew);
    k_scan<<<1, 1024>>>();
    k_fill<<<(EE + TB - 1) / TB, TB>>>(ei, ew);

    // layer 1: h1 = x @ W1 (tf32 tensor cores) ; aggregate -> xemb
    k_gemm1_tf32<<<(NN + 127) / 128, TB>>>(x, W1);
    k_agg1<<<(NN * 32 + TB - 1) / TB, TB>>>(xemb, b1);

    // layer 2: h2 = relu(xemb) @ W2 (scalar fp32) ; aggregate -> out
    k_gemm<HIDD, OUTD, 4, 4, true><<<(NN + 127) / 128, TB>>>(xemb, W2);
    k_agg2<<<(NN * 32 + TB - 1) / TB, TB>>>(outp, b2);
}

// round 16
// speedup vs baseline: 1.2100x; 1.0712x over previous
#include <cuda_runtime.h>
#include <cstdint>

// Problem constants
constexpr int NN   = 100000;   // nodes
constexpr int EE   = 1600000;  // edges
constexpr int IND  = 256;
constexpr int HIDD = 128;
constexpr int OUTD = 32;

typedef unsigned long long ull;

constexpr int TB     = 256;
constexpr int G_DEG  = EE / TB;              // 6250 (exact)
constexpr int G_GEMM = (NN + 127) / 128;     // 782

// Scratch (static device arrays; no allocation allowed)
__device__ ull   g_pdeg[NN];       // packed: cnt<<40 | fixed-point(sum w, 2^20)
__device__ int   g_done;           // deg-block completion counter (self-reset)
__device__ int   g_cnt[NN];        // in-edge count per dst (no self-loop)
__device__ int   g_off[NN];        // CSR row offsets (exclusive prefix of cnt)
__device__ int   g_cur[NN];        // fill cursors
__device__ float g_inv[NN];        // deg^{-1/2}
__device__ int2  g_edge[EE];       // CSR: {src, __float_as_int(norm)} per slot
__device__ float g_h1[(size_t)NN * HIDD];   // x @ W1
__device__ float g_h2[(size_t)NN * OUTD];   // relu(x_emb) @ W2

// ---------------------------------------------------------------------------
// per-block edge dtype probe: true int64 edge_index values all lie in [0,NN);
// int32 read as int64 fuses two indices -> huge values. 16 probes, L2-hit.
// ---------------------------------------------------------------------------
__device__ __forceinline__ int block_probe_is32(const long long* __restrict__ ei,
                                                int* s_flag) {
    if (threadIdx.x == 0) {
        int ok = 1;
        for (int t = 0; t < 16; t++) {
            long long v = ei[t];
            if (v < 0 || v >= NN) { ok = 0; break; }
        }
        *s_flag = ok ? 0 : 1;
    }
    __syncthreads();
    return *s_flag;
}

__device__ __forceinline__ int load_idx(const long long* ei, size_t pos, int is32) {
    return is32 ? ((const int*)ei)[pos] : (int)ei[pos];
}

// tf32 round-to-nearest conversion (result stays in a 32-bit float container)
__device__ __forceinline__ float to_tf32(float f) {
    unsigned o;
    asm("cvt.rna.tf32.f32 %0, %1;" : "=r"(o) : "f"(f));
    return __uint_as_float(o);
}

// ---------------------------------------------------------------------------
// FUSED kernel 1:
//   blocks [0, G_DEG)          : degree accumulation (packed 64-bit atomic);
//                                the LAST deg block then runs the scan
//                                (unpack -> cnt/inv, prefix -> off/cur) while
//                                gemm blocks continue on other SMs.
//   blocks [G_DEG, G_DEG+G_GEMM): tf32 tensor-core GEMM1 h1 = x @ W1
//                                with fragment-ordered shared memory (each
//                                mma fragment = one LDS.128 / LDS.64).
// ---------------------------------------------------------------------------
__global__ __launch_bounds__(256, 2)
void k_fused1(const float* __restrict__ X, const float* __restrict__ W,
              const long long* __restrict__ ei, const float* __restrict__ ew) {
    // ---- shared memory union ----
    __shared__ __align__(16) float sA[4096];   // A fragments: 4 kg x 8 mb x 128
    __shared__ __align__(16) float sB[4096];   // B fragments: 4 kg x 16 nb x 64
    __shared__ int s_misc[257];                // deg path: probe flag + scan sums

    int tid = threadIdx.x;

    if (blockIdx.x < G_DEG) {
        // ================= degree path =================
        int is32 = block_probe_is32(ei, &s_misc[256]);
        int e = blockIdx.x * TB + tid;
        // e < EE always (G_DEG * TB == EE)
        int d = load_idx(ei, (size_t)EE + e, is32);
        if ((unsigned)d < (unsigned)NN) {
            unsigned wq = __float2uint_rn(ew[e] * 1048576.0f);   // 2^20 fixed pt
            atomicAdd(&g_pdeg[d], ((ull)1 << 40) | (ull)wq);
        }
        __threadfence();
        __syncthreads();
        if (tid == 0)
            s_misc[256] = (atomicAdd(&g_done, 1) == G_DEG - 1) ? 1 : 0;
        __syncthreads();
        if (!s_misc[256]) return;

        // ---- last deg block: scan (runs concurrent with gemm blocks) ----
        __threadfence();
        // phase 1: coalesced unpack pdeg -> cnt/inv, reset pdeg
        for (int i = tid; i < NN; i += TB) {
            ull p = g_pdeg[i];
            g_pdeg[i] = 0;
            int c = (int)(p >> 40);
            float dg = 1.0f + (float)(p & 0xFFFFFFFFFFull) * (1.0f / 1048576.0f);
            g_inv[i] = rsqrtf(dg);
            g_cnt[i] = c;
        }
        __syncthreads();
        // phase 2: per-chunk sums (L2-resident reads)
        const int CH = (NN + TB - 1) / TB;       // 391
        int lo = tid * CH;
        int hi = lo + CH < NN ? lo + CH : NN;
        int s = 0;
        for (int i = lo; i < hi; i++) s += g_cnt[i];
        s_misc[tid] = s;
        __syncthreads();
        if (tid == 0) {
            int run = 0;
            for (int i = 0; i < TB; i++) { int v = s_misc[i]; s_misc[i] = run; run += v; }
            g_done = 0;                           // reset for next replay
        }
        __syncthreads();
        int run = s_misc[tid];
        for (int i = lo; i < hi; i++) {
            g_off[i] = run;
            g_cur[i] = run;
            run += g_cnt[i];
        }
        return;
    }

    // ================= gemm path: h1 = x @ W1 (tf32) =================
    constexpr int KK = IND;                   // 256
    int lane = tid & 31, wid = tid >> 5;
    int wm   = wid & 3,  wn  = wid >> 2;      // warp grid 4 (M) x 2 (N)
    int g    = lane >> 2, c  = lane & 3;
    int row0 = (blockIdx.x - G_DEG) * 128;

    float d[2][8][4];
#pragma unroll
    for (int mt = 0; mt < 2; mt++)
#pragma unroll
        for (int nt = 0; nt < 8; nt++)
#pragma unroll
            for (int r = 0; r < 4; r++) d[mt][nt][r] = 0.0f;

    for (int k0 = 0; k0 < KK; k0 += 32) {
        // ---- A g2s, fragment-ordered ----
        // element (k_loc, m_loc) -> frag (kg = k_loc/8, mb = m_loc/16),
        // lane_t = (m_loc&7)*4 + (k_loc&3),
        // reg    = 2*((k_loc&7)>=4) + ((m_loc&15)>=8)
#pragma unroll
        for (int l = 0; l < 4; l++) {
            int idx = tid + l * 256;              // 0..1023
            int r   = idx >> 3;                   // m_loc 0..127
            int kc  = (idx & 7) << 2;             // k_loc base 0..28
            int gr  = row0 + r;
            float4 v = make_float4(0.f, 0.f, 0.f, 0.f);
            if (gr < NN) v = *(const float4*)(X + (size_t)gr * KK + k0 + kc);
            float vv[4] = {v.x, v.y, v.z, v.w};
            int mb = r >> 4;
            int mhalf = (r & 15) >= 8 ? 1 : 0;
            int lbase = (r & 7) << 2;
#pragma unroll
            for (int j = 0; j < 4; j++) {
                int kl = kc + j;
                int kg = kl >> 3;
                int rr = (((kl & 7) >= 4) ? 2 : 0) + mhalf;
                sA[(((kg << 3) + mb) << 7) + ((lbase + (kl & 3)) << 2) + rr] =
                    to_tf32(vv[j]);
            }
        }
        // ---- B g2s, fragment-ordered ----
        // element (k_loc, n_loc) -> frag (kg = k_loc/8, nb = n_loc/8),
        // lane_t = (n_loc&7)*4 + (k_loc&3), reg = ((k_loc&7)>=4)
#pragma unroll
        for (int l = 0; l < 4; l++) {
            int idx = tid + l * 256;              // 0..1023
            int kk  = idx >> 5;                   // k_loc 0..31
            int cc  = (idx & 31) << 2;            // n_loc base 0..124
            float4 v = *(const float4*)(W + (size_t)(k0 + kk) * HIDD + cc);
            float vv[4] = {v.x, v.y, v.z, v.w};
            int kg = kk >> 3;
            int rr = ((kk & 7) >= 4) ? 1 : 0;
            int cl = kk & 3;
#pragma unroll
            for (int j = 0; j < 4; j++) {
                int nl = cc + j;
                sB[(((kg << 4) + (nl >> 3)) << 6) + ((((nl & 7) << 2) + cl) << 1) + rr] =
                    to_tf32(vv[j]);
            }
        }
        __syncthreads();

#pragma unroll
        for (int kg = 0; kg < 4; kg++) {
            unsigned a[2][4];
#pragma unroll
            for (int mt = 0; mt < 2; mt++) {
                float4 av = *(const float4*)(&sA[(((kg << 3) + wm * 2 + mt) << 7) + (lane << 2)]);
                a[mt][0] = __float_as_uint(av.x);
                a[mt][1] = __float_as_uint(av.y);
                a[mt][2] = __float_as_uint(av.z);
                a[mt][3] = __float_as_uint(av.w);
            }
            unsigned b[8][2];
#pragma unroll
            for (int nt = 0; nt < 8; nt++) {
                float2 bv = *(const float2*)(&sB[(((kg << 4) + wn * 8 + nt) << 6) + (lane << 1)]);
                b[nt][0] = __float_as_uint(bv.x);
                b[nt][1] = __float_as_uint(bv.y);
            }
#pragma unroll
            for (int mt = 0; mt < 2; mt++)
#pragma unroll
                for (int nt = 0; nt < 8; nt++) {
                    asm volatile(
                        "mma.sync.aligned.m16n8k8.row.col.f32.tf32.tf32.f32 "
                        "{%0,%1,%2,%3}, {%4,%5,%6,%7}, {%8,%9}, {%0,%1,%2,%3};"
                        : "+f"(d[mt][nt][0]), "+f"(d[mt][nt][1]),
                          "+f"(d[mt][nt][2]), "+f"(d[mt][nt][3])
                        : "r"(a[mt][0]), "r"(a[mt][1]), "r"(a[mt][2]), "r"(a[mt][3]),
                          "r"(b[nt][0]), "r"(b[nt][1]));
                }
        }
        __syncthreads();
    }

    // epilogue: c0,c1 -> (row g, cols 2c,2c+1); c2,c3 -> (row g+8)
#pragma unroll
    for (int mt = 0; mt < 2; mt++) {
        int r0 = row0 + wm * 32 + mt * 16 + g;
        int r1 = r0 + 8;
#pragma unroll
        for (int nt = 0; nt < 8; nt++) {
            int col = wn * 64 + nt * 8 + 2 * c;
            if (r0 < NN) {
                float2 v0 = make_float2(d[mt][nt][0], d[mt][nt][1]);
                *(float2*)(g_h1 + (size_t)r0 * HIDD + col) = v0;
            }
            if (r1 < NN) {
                float2 v1 = make_float2(d[mt][nt][2], d[mt][nt][3]);
                *(float2*)(g_h1 + (size_t)r1 * HIDD + col) = v1;
            }
        }
    }
}

// ---------------------------------------------------------------------------
// scatter edges into CSR slots; one packed 8B store per edge
// ---------------------------------------------------------------------------
__global__ void k_fill(const long long* __restrict__ ei, const float* __restrict__ ew) {
    __shared__ int s_is32;
    int is32 = block_probe_is32(ei, &s_is32);
    int e = blockIdx.x * blockDim.x + threadIdx.x;
    if (e < EE) {
        int s = load_idx(ei, (size_t)e, is32);
        int d = load_idx(ei, (size_t)EE + e, is32);
        if ((unsigned)s < (unsigned)NN && (unsigned)d < (unsigned)NN) {
            int pos = atomicAdd(&g_cur[d], 1);
            float nw = g_inv[s] * ew[e] * g_inv[d];
            g_edge[pos] = make_int2(s, __float_as_int(nw));
        }
    }
}

// ---------------------------------------------------------------------------
// Scalar fp32 GEMM — layer 2 only: g_h2 = relu(xemb) @ W2
// ---------------------------------------------------------------------------
template <int KK, int BN, int TM, int TN, bool RELU>
__global__ __launch_bounds__(256)
void k_gemm(const float* __restrict__ X, const float* __restrict__ W) {
    float* __restrict__ H = g_h2;

    constexpr int KT = 16;
    constexpr int BM = 128;
    constexpr int TX = BN / TN;
    constexpr int TY = 256 / TX;

    __shared__ __align__(16) float As[KT][BM + 4];
    __shared__ __align__(16) float Bs[KT][BN];

    int tid  = threadIdx.x;
    int tx   = tid % TX;
    int ty   = tid / TX;
    int row0 = blockIdx.x * BM;

    float acc[TM][TN];
#pragma unroll
    for (int i = 0; i < TM; i++)
#pragma unroll
        for (int j = 0; j < TN; j++) acc[i][j] = 0.0f;

    for (int k0 = 0; k0 < KK; k0 += KT) {
        constexpr int XF4 = BM * KT / 4;
#pragma unroll
        for (int l = 0; l < XF4 / 256; l++) {
            int idx = tid + l * 256;
            int r   = idx >> 2;
            int kc  = (idx & 3) << 2;
            int gr  = row0 + r;
            float4 v = make_float4(0.f, 0.f, 0.f, 0.f);
            if (gr < NN) v = *(const float4*)(X + (size_t)gr * KK + k0 + kc);
            if (RELU) {
                v.x = fmaxf(v.x, 0.f); v.y = fmaxf(v.y, 0.f);
                v.z = fmaxf(v.z, 0.f); v.w = fmaxf(v.w, 0.f);
            }
            As[kc + 0][r] = v.x; As[kc + 1][r] = v.y;
            As[kc + 2][r] = v.z; As[kc + 3][r] = v.w;
        }
        constexpr int WF4 = KT * BN / 4;
#pragma unroll
        for (int l = 0; l < (WF4 + 255) / 256; l++) {
            int idx = tid + l * 256;
            if (idx < WF4) {
                int kk = idx / (BN / 4);
                int cc = (idx % (BN / 4)) * 4;
                *(float4*)(&Bs[kk][cc]) = *(const float4*)(W + (size_t)(k0 + kk) * BN + cc);
            }
        }
        __syncthreads();

#pragma unroll
        for (int k = 0; k < KT; k++) {
            float a[TM], b[TN];
#pragma unroll
            for (int i = 0; i < TM / 4; i++)
                *(float4*)(a + 4 * i) = *(const float4*)(&As[k][ty * TM + 4 * i]);
#pragma unroll
            for (int j = 0; j < TN / 4; j++)
                *(float4*)(b + 4 * j) = *(const float4*)(&Bs[k][tx * TN + 4 * j]);
#pragma unroll
            for (int i = 0; i < TM; i++)
#pragma unroll
                for (int j = 0; j < TN; j++) acc[i][j] += a[i] * b[j];
        }
        __syncthreads();
    }

#pragma unroll
    for (int i = 0; i < TM; i++) {
        int gr = row0 + ty * TM + i;
        if (gr < NN) {
#pragma unroll
            for (int j = 0; j < TN / 4; j++) {
                float4 v = make_float4(acc[i][4 * j], acc[i][4 * j + 1],
                                       acc[i][4 * j + 2], acc[i][4 * j + 3]);
                *(float4*)(H + (size_t)gr * BN + tx * TN + 4 * j) = v;
            }
        }
    }
}

// ---------------------------------------------------------------------------
// CSR aggregation, layer 1 (unroll-4): one warp per node, lane owns float4.
// out = sum_{e in in(n)} norm_e * h1[src_e] + inv(n)^2 * h1[n] + b1
// ---------------------------------------------------------------------------
__global__ void k_agg1(float* __restrict__ xemb, const float* __restrict__ b1) {
    int warp = (blockIdx.x * blockDim.x + threadIdx.x) >> 5;
    int lane = threadIdx.x & 31;
    if (warp >= NN) return;

    int beg = g_off[warp];
    int cnt = g_cnt[warp];
    float iv = g_inv[warp];
    float inv2 = iv * iv;

    size_t off = (size_t)warp * HIDD + lane * 4;
    float4 h = *(const float4*)(g_h1 + off);
    float4 b = *(const float4*)(b1 + lane * 4);
    float4 acc;
    acc.x = inv2 * h.x + b.x;
    acc.y = inv2 * h.y + b.y;
    acc.z = inv2 * h.z + b.z;
    acc.w = inv2 * h.w + b.w;

    int i = 0;
    for (; i + 4 <= cnt; i += 4) {
        int2 p0 = g_edge[beg + i + 0], p1 = g_edge[beg + i + 1];
        int2 p2 = g_edge[beg + i + 2], p3 = g_edge[beg + i + 3];
        float n0 = __int_as_float(p0.y), n1 = __int_as_float(p1.y);
        float n2 = __int_as_float(p2.y), n3 = __int_as_float(p3.y);
        float4 v0 = *(const float4*)(g_h1 + (size_t)p0.x * HIDD + lane * 4);
        float4 v1 = *(const float4*)(g_h1 + (size_t)p1.x * HIDD + lane * 4);
        float4 v2 = *(const float4*)(g_h1 + (size_t)p2.x * HIDD + lane * 4);
        float4 v3 = *(const float4*)(g_h1 + (size_t)p3.x * HIDD + lane * 4);
        acc.x += n0 * v0.x + n1 * v1.x + n2 * v2.x + n3 * v3.x;
        acc.y += n0 * v0.y + n1 * v1.y + n2 * v2.y + n3 * v3.y;
        acc.z += n0 * v0.z + n1 * v1.z + n2 * v2.z + n3 * v3.z;
        acc.w += n0 * v0.w + n1 * v1.w + n2 * v2.w + n3 * v3.w;
    }
    for (; i < cnt; i++) {
        int2 p = g_edge[beg + i];
        float nw = __int_as_float(p.y);
        float4 v = *(const float4*)(g_h1 + (size_t)p.x * HIDD + lane * 4);
        acc.x += nw * v.x; acc.y += nw * v.y;
        acc.z += nw * v.z; acc.w += nw * v.w;
    }
    *(float4*)(xemb + off) = acc;
}

// layer 2: 32 features -> one float per lane (unroll-4)
__global__ void k_agg2(float* __restrict__ outp, const float* __restrict__ b2) {
    int warp = (blockIdx.x * blockDim.x + threadIdx.x) >> 5;
    int lane = threadIdx.x & 31;
    if (warp >= NN) return;

    int beg = g_off[warp];
    int cnt = g_cnt[warp];
    float iv = g_inv[warp];
    float inv2 = iv * iv;

    size_t off = (size_t)warp * OUTD + lane;
    float acc = inv2 * g_h2[off] + b2[lane];

    int i = 0;
    for (; i + 4 <= cnt; i += 4) {
        int2 p0 = g_edge[beg + i + 0], p1 = g_edge[beg + i + 1];
        int2 p2 = g_edge[beg + i + 2], p3 = g_edge[beg + i + 3];
        acc += __int_as_float(p0.y) * g_h2[(size_t)p0.x * OUTD + lane]
             + __int_as_float(p1.y) * g_h2[(size_t)p1.x * OUTD + lane]
             + __int_as_float(p2.y) * g_h2[(size_t)p2.x * OUTD + lane]
             + __int_as_float(p3.y) * g_h2[(size_t)p3.x * OUTD + lane];
    }
    for (; i < cnt; i++) {
        int2 p = g_edge[beg + i];
        acc += __int_as_float(p.y) * g_h2[(size_t)p.x * OUTD + lane];
    }
    outp[off] = acc;
}

// ---------------------------------------------------------------------------
extern "C" void kernel_launch(void* const* d_in, const int* in_sizes, int n_in,
                              void* d_out, int out_size) {
    const float*     x  = (const float*)d_in[0];
    const long long* ei = (const long long*)d_in[1];   // int32 or int64 — probed
    const float*     ew = (const float*)d_in[2];
    const float*     W1 = (const float*)d_in[3];
    const float*     b1 = (const float*)d_in[4];
    const float*     W2 = (const float*)d_in[5];
    const float*     b2 = (const float*)d_in[6];

    float* outp = (float*)d_out;                       // [NN, OUTD]
    float* xemb = outp + (size_t)NN * OUTD;            // [NN, HIDD]

    // fused: degree (+last-block scan) || tf32 gemm1
    k_fused1<<<G_DEG + G_GEMM, TB>>>(x, W1, ei, ew);
    // CSR fill (needs scan complete)
    k_fill<<<(EE + TB - 1) / TB, TB>>>(ei, ew);
    // layer 1 aggregate (+self-loop +bias) -> xemb
    k_agg1<<<(NN * 32 + TB - 1) / TB, TB>>>(xemb, b1);
    // layer 2: h2 = relu(xemb) @ W2 ; aggregate -> out
    k_gemm<HIDD, OUTD, 4, 4, true><<<(NN + 127) / 128, TB>>>(xemb, W2);
    k_agg2<<<(NN * 32 + TB - 1) / TB, TB>>>(outp, b2);
}